// round 1
// baseline (speedup 1.0000x reference)
#include <cuda_runtime.h>
#include <math.h>

#define NN 100000
#define EE 1600000
#define ET (EE + NN)          // edges incl. self-loops = 1,700,000
#define F  64                 // feature width after both linears

// ---------------- scratch (device globals: no allocation allowed) -----------
__device__ float g_xW[NN * F];    // features after linear (reused both layers)
__device__ float g_h[NN * F];     // layer-0 output (input to layer 1)
__device__ float g_agg[NN * F];   // aggregation accumulator
__device__ float g_as[NN * 8];    // per-node src attention logits (stride H)
__device__ float g_ad[NN * 8];    // per-node dst attention logits
__device__ float g_m[NN * 8];     // segment max
__device__ float g_den[NN * 8];   // segment exp-sum

__device__ __forceinline__ void atomicMaxF(float* addr, float val) {
    int* ai = (int*)addr;
    int old = *ai;
    while (__int_as_float(old) < val) {
        int assumed = old;
        old = atomicCAS(ai, assumed, __float_as_int(val));
        if (old == assumed) break;
    }
}

__device__ __forceinline__ float leaky(float v) { return v > 0.f ? v : 0.2f * v; }
__device__ __forceinline__ float elu(float v)   { return v > 0.f ? v : expm1f(v); }

// ---------------- layer-0 linear: x[N,128] @ W0[128,64], + attn dots --------
__global__ void lin0_kernel(const float* __restrict__ x,
                            const float* __restrict__ W0,
                            const float* __restrict__ asw,   // [64] = [H=8,C=8]
                            const float* __restrict__ adw) {
    int n = blockIdx.x;
    int c = threadIdx.x;               // 64 threads
    __shared__ float xs[128];
    xs[c]      = x[n * 128 + c];
    xs[c + 64] = x[n * 128 + 64 + c];
    __syncthreads();
    float acc = 0.f;
#pragma unroll 8
    for (int k = 0; k < 128; k++) acc = fmaf(xs[k], W0[k * 64 + c], acc);
    g_xW[n * 64 + c] = acc;
    float ps = acc * asw[c];
    float pd = acc * adw[c];
    // reduce within 8-lane groups (one head per group)
#pragma unroll
    for (int off = 4; off > 0; off >>= 1) {
        ps += __shfl_down_sync(0xFFFFFFFFu, ps, off, 8);
        pd += __shfl_down_sync(0xFFFFFFFFu, pd, off, 8);
    }
    if ((c & 7) == 0) {
        g_as[n * 8 + (c >> 3)] = ps;
        g_ad[n * 8 + (c >> 3)] = pd;
    }
}

// ---------------- layer-1 linear: h[N,64] @ W1[64,64], + attn dots (H=1) ----
__global__ void lin1_kernel(const float* __restrict__ W1,
                            const float* __restrict__ asw,   // [64]
                            const float* __restrict__ adw) {
    int n = blockIdx.x;
    int c = threadIdx.x;               // 64 threads
    __shared__ float hs[64];
    __shared__ float reds[2], redd[2];
    hs[c] = g_h[n * 64 + c];
    __syncthreads();
    float acc = 0.f;
#pragma unroll 8
    for (int k = 0; k < 64; k++) acc = fmaf(hs[k], W1[k * 64 + c], acc);
    g_xW[n * 64 + c] = acc;
    float ps = acc * asw[c];
    float pd = acc * adw[c];
#pragma unroll
    for (int off = 16; off > 0; off >>= 1) {
        ps += __shfl_down_sync(0xFFFFFFFFu, ps, off, 32);
        pd += __shfl_down_sync(0xFFFFFFFFu, pd, off, 32);
    }
    int lane = c & 31, w = c >> 5;
    if (lane == 0) { reds[w] = ps; redd[w] = pd; }
    __syncthreads();
    if (c == 0) {
        g_as[n] = reds[0] + reds[1];
        g_ad[n] = redd[0] + redd[1];
    }
}

// ---------------- init: zero agg, reset max/denom ---------------------------
template <int H>
__global__ void init_kernel() {
    int idx = blockIdx.x * blockDim.x + threadIdx.x;
    if (idx < NN * F) g_agg[idx] = 0.f;
    if (idx < NN * H) { g_m[idx] = -INFINITY; g_den[idx] = 0.f; }
}

// ---------------- edge helpers ----------------------------------------------
__device__ __forceinline__ void edge_sd(const int* __restrict__ ei, int e, int& s, int& d) {
    if (e < EE) { s = ei[e]; d = ei[EE + e]; }
    else        { s = e - EE; d = s; }
}

template <int H>
__global__ void edge_max_kernel(const int* __restrict__ ei) {
    int idx = blockIdx.x * blockDim.x + threadIdx.x;
    if (idx >= ET * H) return;
    int e = idx / H, h = idx - e * H;
    int s, d; edge_sd(ei, e, s, d);
    float v = leaky(g_as[s * H + h] + g_ad[d * H + h]);
    atomicMaxF(&g_m[d * H + h], v);
}

template <int H>
__global__ void edge_sum_kernel(const int* __restrict__ ei) {
    int idx = blockIdx.x * blockDim.x + threadIdx.x;
    if (idx >= ET * H) return;
    int e = idx / H, h = idx - e * H;
    int s, d; edge_sd(ei, e, s, d);
    float v = leaky(g_as[s * H + h] + g_ad[d * H + h]);
    atomicAdd(&g_den[d * H + h], expf(v - g_m[d * H + h]));
}

template <int H>
__global__ void edge_agg_kernel(const int* __restrict__ ei) {
    int idx = blockIdx.x * blockDim.x + threadIdx.x;
    if (idx >= ET * F) return;
    int e = idx >> 6, c = idx & 63;
    int h = (c * H) >> 6;              // H=8 -> c/8 ; H=1 -> 0
    int s, d; edge_sd(ei, e, s, d);
    float v = leaky(g_as[s * H + h] + g_ad[d * H + h]);
    float alpha = expf(v - g_m[d * H + h]) / g_den[d * H + h];
    atomicAdd(&g_agg[d * 64 + c], alpha * g_xW[s * 64 + c]);
}

// ---------------- finalize: + bias, ELU --------------------------------------
__global__ void fin0_kernel(const float* __restrict__ b) {
    int idx = blockIdx.x * blockDim.x + threadIdx.x;
    if (idx >= NN * F) return;
    g_h[idx] = elu(g_agg[idx] + b[idx & 63]);
}

__global__ void fin1_kernel(float* __restrict__ out, const float* __restrict__ b) {
    int idx = blockIdx.x * blockDim.x + threadIdx.x;
    if (idx >= NN * F) return;
    out[idx] = elu(g_agg[idx] + b[idx & 63]);
}

// ---------------- launch ------------------------------------------------------
extern "C" void kernel_launch(void* const* d_in, const int* in_sizes, int n_in,
                              void* d_out, int out_size) {
    const float* x   = (const float*)d_in[0];
    const int*   ei  = (const int*)  d_in[1];
    const float* W0  = (const float*)d_in[2];
    const float* as0 = (const float*)d_in[3];
    const float* ad0 = (const float*)d_in[4];
    const float* b0  = (const float*)d_in[5];
    const float* W1  = (const float*)d_in[6];
    const float* as1 = (const float*)d_in[7];
    const float* ad1 = (const float*)d_in[8];
    const float* b1  = (const float*)d_in[9];
    float* out = (float*)d_out;

    const int TB = 256;
    int g_nf  = (NN * F + TB - 1) / TB;           // node*feature grid
    int g_e8  = (ET * 8 + TB - 1) / TB;           // edge*head(8) grid
    int g_e1  = (ET * 1 + TB - 1) / TB;           // edge*head(1) grid
    int g_ef  = (ET * F + TB - 1) / TB;           // edge*feature grid

    // ---- layer 0 (H=8, C=8) ----
    lin0_kernel<<<NN, 64>>>(x, W0, as0, ad0);
    init_kernel<8><<<g_nf, TB>>>();
    edge_max_kernel<8><<<g_e8, TB>>>(ei);
    edge_sum_kernel<8><<<g_e8, TB>>>(ei);
    edge_agg_kernel<8><<<g_ef, TB>>>(ei);
    fin0_kernel<<<g_nf, TB>>>(b0);

    // ---- layer 1 (H=1, C=64) ----
    lin1_kernel<<<NN, 64>>>(W1, as1, ad1);
    init_kernel<1><<<g_nf, TB>>>();
    edge_max_kernel<1><<<g_e1, TB>>>(ei);
    edge_sum_kernel<1><<<g_e1, TB>>>(ei);
    edge_agg_kernel<1><<<g_ef, TB>>>(ei);
    fin1_kernel<<<g_nf, TB>>>(out, b1);
}

// round 2
// speedup vs baseline: 1.7017x; 1.7017x over previous
#include <cuda_runtime.h>
#include <math.h>

#define NN 100000
#define EE 1600000
#define ET (EE + NN)          // edges incl. self-loops = 1,700,000
#define F  64

// ---------------- scratch (device globals, 16B aligned for vector red) ------
__device__ __align__(16) float    g_xW[NN * F];
__device__ __align__(16) float    g_h[NN * F];
__device__ __align__(16) float    g_agg[NN * F];
__device__ __align__(16) float    g_as[NN * 8];
__device__ __align__(16) float    g_ad[NN * 8];
__device__ __align__(16) unsigned g_m[NN * 8];    // monotone-encoded max
__device__ __align__(16) float    g_den[NN * 8];

// order-preserving float <-> uint encoding (monotone under unsigned compare)
__device__ __forceinline__ unsigned fenc(float v) {
    unsigned b = __float_as_uint(v);
    return (b & 0x80000000u) ? ~b : (b | 0x80000000u);
}
__device__ __forceinline__ float fdec(unsigned u) {
    return (u & 0x80000000u) ? __uint_as_float(u & 0x7FFFFFFFu) : __uint_as_float(~u);
}
#define ENC_NEG_INF 0x007FFFFFu   // fenc(-inf)

__device__ __forceinline__ float leaky(float v) { return v > 0.f ? v : 0.2f * v; }
__device__ __forceinline__ float elu(float v)   { return v > 0.f ? v : expm1f(v); }

__device__ __forceinline__ void red_add_v4(float* addr, float4 v) {
    asm volatile("red.global.add.v4.f32 [%0], {%1,%2,%3,%4};"
                 :: "l"(addr), "f"(v.x), "f"(v.y), "f"(v.z), "f"(v.w) : "memory");
}

__device__ __forceinline__ void edge_sd(const int* __restrict__ ei, int e, int& s, int& d) {
    if (e < EE) { s = __ldg(&ei[e]); d = __ldg(&ei[EE + e]); }
    else        { s = e - EE; d = s; }
}

// ---------------- layer-0 linear: x[N,128] @ W0[128,64], + attn dots --------
__global__ void lin0_kernel(const float* __restrict__ x,
                            const float* __restrict__ W0,
                            const float* __restrict__ asw,
                            const float* __restrict__ adw) {
    int n = blockIdx.x;
    int c = threadIdx.x;               // 64 threads
    __shared__ float xs[128];
    xs[c]      = x[n * 128 + c];
    xs[c + 64] = x[n * 128 + 64 + c];
    __syncthreads();
    float acc = 0.f;
#pragma unroll 8
    for (int k = 0; k < 128; k++) acc = fmaf(xs[k], W0[k * 64 + c], acc);
    g_xW[n * 64 + c] = acc;
    float ps = acc * asw[c];
    float pd = acc * adw[c];
#pragma unroll
    for (int off = 4; off > 0; off >>= 1) {
        ps += __shfl_down_sync(0xFFFFFFFFu, ps, off, 8);
        pd += __shfl_down_sync(0xFFFFFFFFu, pd, off, 8);
    }
    if ((c & 7) == 0) {
        g_as[n * 8 + (c >> 3)] = ps;
        g_ad[n * 8 + (c >> 3)] = pd;
    }
}

// ---------------- layer-1 linear: h[N,64] @ W1[64,64], + attn dots (H=1) ----
__global__ void lin1_kernel(const float* __restrict__ W1,
                            const float* __restrict__ asw,
                            const float* __restrict__ adw) {
    int n = blockIdx.x;
    int c = threadIdx.x;
    __shared__ float hs[64];
    __shared__ float reds[2], redd[2];
    hs[c] = g_h[n * 64 + c];
    __syncthreads();
    float acc = 0.f;
#pragma unroll 8
    for (int k = 0; k < 64; k++) acc = fmaf(hs[k], W1[k * 64 + c], acc);
    g_xW[n * 64 + c] = acc;
    float ps = acc * asw[c];
    float pd = acc * adw[c];
#pragma unroll
    for (int off = 16; off > 0; off >>= 1) {
        ps += __shfl_down_sync(0xFFFFFFFFu, ps, off, 32);
        pd += __shfl_down_sync(0xFFFFFFFFu, pd, off, 32);
    }
    int lane = c & 31, w = c >> 5;
    if (lane == 0) { reds[w] = ps; redd[w] = pd; }
    __syncthreads();
    if (c == 0) {
        g_as[n] = reds[0] + reds[1];
        g_ad[n] = redd[0] + redd[1];
    }
}

// ---------------- init -------------------------------------------------------
template <int H>
__global__ void init_kernel() {
    int idx = blockIdx.x * blockDim.x + threadIdx.x;   // over NN*F/4
    if (idx < NN * F / 4) ((float4*)g_agg)[idx] = make_float4(0.f, 0.f, 0.f, 0.f);
    if (idx < NN * H) { g_m[idx] = ENC_NEG_INF; g_den[idx] = 0.f; }
}

// ---------------- segment max ------------------------------------------------
__global__ void edge_max8(const int* __restrict__ ei) {
    int e = blockIdx.x * blockDim.x + threadIdx.x;
    if (e >= ET) return;
    int s, d; edge_sd(ei, e, s, d);
    float4 a0 = *(const float4*)&g_as[s * 8];
    float4 a1 = *(const float4*)&g_as[s * 8 + 4];
    float4 b0 = *(const float4*)&g_ad[d * 8];
    float4 b1 = *(const float4*)&g_ad[d * 8 + 4];
    unsigned* m = &g_m[d * 8];
    atomicMax(&m[0], fenc(leaky(a0.x + b0.x)));
    atomicMax(&m[1], fenc(leaky(a0.y + b0.y)));
    atomicMax(&m[2], fenc(leaky(a0.z + b0.z)));
    atomicMax(&m[3], fenc(leaky(a0.w + b0.w)));
    atomicMax(&m[4], fenc(leaky(a1.x + b1.x)));
    atomicMax(&m[5], fenc(leaky(a1.y + b1.y)));
    atomicMax(&m[6], fenc(leaky(a1.z + b1.z)));
    atomicMax(&m[7], fenc(leaky(a1.w + b1.w)));
}

__global__ void edge_max1(const int* __restrict__ ei) {
    int e = blockIdx.x * blockDim.x + threadIdx.x;
    if (e >= ET) return;
    int s, d; edge_sd(ei, e, s, d);
    atomicMax(&g_m[d], fenc(leaky(g_as[s] + g_ad[d])));
}

// ---------------- segment exp-sum ---------------------------------------------
__global__ void edge_sum8(const int* __restrict__ ei) {
    int e = blockIdx.x * blockDim.x + threadIdx.x;
    if (e >= ET) return;
    int s, d; edge_sd(ei, e, s, d);
    float4 a0 = *(const float4*)&g_as[s * 8];
    float4 a1 = *(const float4*)&g_as[s * 8 + 4];
    float4 b0 = *(const float4*)&g_ad[d * 8];
    float4 b1 = *(const float4*)&g_ad[d * 8 + 4];
    uint4  m0 = *(const uint4*) &g_m[d * 8];
    uint4  m1 = *(const uint4*) &g_m[d * 8 + 4];
    float4 e0, e1;
    e0.x = expf(leaky(a0.x + b0.x) - fdec(m0.x));
    e0.y = expf(leaky(a0.y + b0.y) - fdec(m0.y));
    e0.z = expf(leaky(a0.z + b0.z) - fdec(m0.z));
    e0.w = expf(leaky(a0.w + b0.w) - fdec(m0.w));
    e1.x = expf(leaky(a1.x + b1.x) - fdec(m1.x));
    e1.y = expf(leaky(a1.y + b1.y) - fdec(m1.y));
    e1.z = expf(leaky(a1.z + b1.z) - fdec(m1.z));
    e1.w = expf(leaky(a1.w + b1.w) - fdec(m1.w));
    red_add_v4(&g_den[d * 8], e0);
    red_add_v4(&g_den[d * 8 + 4], e1);
}

__global__ void edge_sum1(const int* __restrict__ ei) {
    int e = blockIdx.x * blockDim.x + threadIdx.x;
    if (e >= ET) return;
    int s, d; edge_sd(ei, e, s, d);
    atomicAdd(&g_den[d], expf(leaky(g_as[s] + g_ad[d]) - fdec(g_m[d])));
}

// ---------------- weighted aggregation: 16 threads per edge, float4 ----------
template <int H>
__global__ void edge_agg_kernel(const int* __restrict__ ei) {
    long long idx = (long long)blockIdx.x * blockDim.x + threadIdx.x;
    if (idx >= (long long)ET * 16) return;
    int e = (int)(idx >> 4), q = (int)(idx & 15);
    int s, d; edge_sd(ei, e, s, d);
    int h = (H == 8) ? (q >> 1) : 0;
    float v = leaky(g_as[s * H + h] + g_ad[d * H + h]);
    float alpha = expf(v - fdec(g_m[d * H + h])) / g_den[d * H + h];
    float4 f = *(const float4*)&g_xW[s * 64 + q * 4];
    f.x *= alpha; f.y *= alpha; f.z *= alpha; f.w *= alpha;
    red_add_v4(&g_agg[d * 64 + q * 4], f);
}

// ---------------- finalize ----------------------------------------------------
__global__ void fin0_kernel(const float* __restrict__ b) {
    int idx = blockIdx.x * blockDim.x + threadIdx.x;
    if (idx >= NN * F) return;
    g_h[idx] = elu(g_agg[idx] + b[idx & 63]);
}

__global__ void fin1_kernel(float* __restrict__ out, const float* __restrict__ b) {
    int idx = blockIdx.x * blockDim.x + threadIdx.x;
    if (idx >= NN * F) return;
    out[idx] = elu(g_agg[idx] + b[idx & 63]);
}

// ---------------- launch ------------------------------------------------------
extern "C" void kernel_launch(void* const* d_in, const int* in_sizes, int n_in,
                              void* d_out, int out_size) {
    const float* x   = (const float*)d_in[0];
    const int*   ei  = (const int*)  d_in[1];
    const float* W0  = (const float*)d_in[2];
    const float* as0 = (const float*)d_in[3];
    const float* ad0 = (const float*)d_in[4];
    const float* b0  = (const float*)d_in[5];
    const float* W1  = (const float*)d_in[6];
    const float* as1 = (const float*)d_in[7];
    const float* ad1 = (const float*)d_in[8];
    const float* b1  = (const float*)d_in[9];
    float* out = (float*)d_out;

    const int TB = 256;
    int g_nf = (NN * F + TB - 1) / TB;
    int g_e  = (ET + TB - 1) / TB;
    long long ef = (long long)ET * 16;
    int g_ef = (int)((ef + TB - 1) / TB);

    // ---- layer 0 (H=8, C=8) ----
    lin0_kernel<<<NN, 64>>>(x, W0, as0, ad0);
    init_kernel<8><<<g_nf, TB>>>();
    edge_max8<<<g_e, TB>>>(ei);
    edge_sum8<<<g_e, TB>>>(ei);
    edge_agg_kernel<8><<<g_ef, TB>>>(ei);
    fin0_kernel<<<g_nf, TB>>>(b0);

    // ---- layer 1 (H=1, C=64) ----
    lin1_kernel<<<NN, 64>>>(W1, as1, ad1);
    init_kernel<1><<<g_nf, TB>>>();
    edge_max1<<<g_e, TB>>>(ei);
    edge_sum1<<<g_e, TB>>>(ei);
    edge_agg_kernel<1><<<g_ef, TB>>>(ei);
    fin1_kernel<<<g_nf, TB>>>(out, b1);
}

// round 5
// speedup vs baseline: 2.0179x; 1.1858x over previous
#include <cuda_runtime.h>
#include <math.h>

#define NN 100000
#define EE 1600000
#define ET (EE + NN)          // edges incl. self-loops
#define FULL 0xFFFFFFFFu

// ---------------- scratch (device globals) -----------------------------------
__device__ __align__(16) float g_xW[NN * 64];   // features after linear
__device__ __align__(16) float g_h[NN * 64];    // layer-0 output
__device__ __align__(16) float g_as[NN * 8];    // src attention logits
__device__ __align__(16) float g_ad[NN * 8];    // dst attention logits
__device__ int g_cnt[NN];
__device__ int g_off[NN + 1];
__device__ int g_woff[NN];
__device__ int g_srcs[ET];

__device__ __forceinline__ float leaky(float v) { return v > 0.f ? v : 0.2f * v; }
__device__ __forceinline__ float elu(float v)   { return v > 0.f ? v : expm1f(v); }

__device__ __forceinline__ void edge_sd(const int* __restrict__ ei, int e, int& s, int& d) {
    if (e < EE) { s = __ldg(&ei[e]); d = __ldg(&ei[EE + e]); }
    else        { s = e - EE; d = s; }
}

__device__ __forceinline__ float dot4(float4 a, float4 b, float acc) {
    return fmaf(a.x, b.x, fmaf(a.y, b.y, fmaf(a.z, b.z, fmaf(a.w, b.w, acc))));
}

// ================= CSR build (counting sort by dst) ===========================
__global__ void zero_cnt_kernel() {
    int i = blockIdx.x * blockDim.x + threadIdx.x;
    if (i < NN) g_cnt[i] = 0;
}

__global__ void hist_kernel(const int* __restrict__ ei) {
    int e = blockIdx.x * blockDim.x + threadIdx.x;
    if (e >= ET) return;
    int s, d; edge_sd(ei, e, s, d);
    atomicAdd(&g_cnt[d], 1);
}

__global__ void scan_kernel() {
    __shared__ int sums[1024];
    int t = threadIdx.x;
    const int CH = (NN + 1023) / 1024;
    int beg = t * CH, end = min(beg + CH, NN);
    int s = 0;
    for (int i = beg; i < end; i++) s += g_cnt[i];
    sums[t] = s;
    __syncthreads();
    for (int off = 1; off < 1024; off <<= 1) {
        int v = (t >= off) ? sums[t - off] : 0;
        __syncthreads();
        sums[t] += v;
        __syncthreads();
    }
    int run = sums[t] - s;               // exclusive base
    for (int i = beg; i < end; i++) {
        g_off[i] = run; g_woff[i] = run;
        run += g_cnt[i];
    }
    if (t == 0) g_off[NN] = ET;
}

__global__ void scatter_kernel(const int* __restrict__ ei) {
    int e = blockIdx.x * blockDim.x + threadIdx.x;
    if (e >= ET) return;
    int s, d; edge_sd(ei, e, s, d);
    int pos = atomicAdd(&g_woff[d], 1);
    g_srcs[pos] = s;
}

// ================= layer-0 linear: x[N,128] @ W0[128,64] ======================
__global__ __launch_bounds__(256) void lin0_kernel(const float* __restrict__ x,
                                                   const float* __restrict__ W0) {
    __shared__ float W0t[64 * 132];      // transposed, padded: W0t[c*132+k]
    __shared__ float xs[16 * 128];
    int t = threadIdx.x;
    for (int i = t; i < 128 * 64; i += 256) {
        int k = i >> 6, c = i & 63;
        W0t[c * 132 + k] = W0[i];
    }
    int c  = t & 15;
    int nl = t >> 4;
    int nodeBase = blockIdx.x * 64;
    for (int g = 0; g < 4; g++) {
        int base = nodeBase + g * 16;
        __syncthreads();
        for (int i = t; i < 512; i += 256) {       // 16 nodes x 32 float4
            int nn2 = i >> 5, kv = i & 31;
            int nd = base + nn2;
            float4 v = (nd < NN) ? ((const float4*)x)[nd * 32 + kv]
                                 : make_float4(0.f, 0.f, 0.f, 0.f);
            ((float4*)xs)[i] = v;
        }
        __syncthreads();
        int node = base + nl;
        if (node < NN) {
            float a0 = 0.f, a1 = 0.f, a2 = 0.f, a3 = 0.f;
#pragma unroll 8
            for (int k = 0; k < 128; k += 4) {
                float4 xv = *(const float4*)&xs[nl * 128 + k];
                a0 = dot4(xv, *(const float4*)&W0t[c * 132 + k],        a0);
                a1 = dot4(xv, *(const float4*)&W0t[(c + 16) * 132 + k], a1);
                a2 = dot4(xv, *(const float4*)&W0t[(c + 32) * 132 + k], a2);
                a3 = dot4(xv, *(const float4*)&W0t[(c + 48) * 132 + k], a3);
            }
            g_xW[node * 64 + c]      = a0;
            g_xW[node * 64 + c + 16] = a1;
            g_xW[node * 64 + c + 32] = a2;
            g_xW[node * 64 + c + 48] = a3;
        }
    }
}

// ================= layer-1 linear: h[N,64] @ W1[64,64] ========================
__global__ __launch_bounds__(256) void lin1_kernel(const float* __restrict__ W1) {
    __shared__ float W1t[64 * 68];
    __shared__ float hs[16 * 64];
    int t = threadIdx.x;
    for (int i = t; i < 64 * 64; i += 256) {
        int k = i >> 6, c = i & 63;
        W1t[c * 68 + k] = W1[i];
    }
    int c  = t & 15;
    int nl = t >> 4;
    int nodeBase = blockIdx.x * 64;
    for (int g = 0; g < 4; g++) {
        int base = nodeBase + g * 16;
        __syncthreads();
        for (int i = t; i < 256; i += 256) {       // 16 nodes x 16 float4
            int nn2 = i >> 4, kv = i & 15;
            int nd = base + nn2;
            float4 v = (nd < NN) ? ((const float4*)g_h)[nd * 16 + kv]
                                 : make_float4(0.f, 0.f, 0.f, 0.f);
            ((float4*)hs)[i] = v;
        }
        __syncthreads();
        int node = base + nl;
        if (node < NN) {
            float a0 = 0.f, a1 = 0.f, a2 = 0.f, a3 = 0.f;
#pragma unroll 8
            for (int k = 0; k < 64; k += 4) {
                float4 xv = *(const float4*)&hs[nl * 64 + k];
                a0 = dot4(xv, *(const float4*)&W1t[c * 68 + k],        a0);
                a1 = dot4(xv, *(const float4*)&W1t[(c + 16) * 68 + k], a1);
                a2 = dot4(xv, *(const float4*)&W1t[(c + 32) * 68 + k], a2);
                a3 = dot4(xv, *(const float4*)&W1t[(c + 48) * 68 + k], a3);
            }
            g_xW[node * 64 + c]      = a0;
            g_xW[node * 64 + c + 16] = a1;
            g_xW[node * 64 + c + 32] = a2;
            g_xW[node * 64 + c + 48] = a3;
        }
    }
}

// ================= attention dots =============================================
__global__ void att0_kernel(const float* __restrict__ asw, const float* __restrict__ adw) {
    int idx = blockIdx.x * blockDim.x + threadIdx.x;
    if (idx >= NN * 64) return;
    int c = idx & 63;
    float acc = g_xW[idx];
    float ps = acc * __ldg(&asw[c]);
    float pd = acc * __ldg(&adw[c]);
#pragma unroll
    for (int off = 4; off > 0; off >>= 1) {
        ps += __shfl_down_sync(FULL, ps, off, 8);
        pd += __shfl_down_sync(FULL, pd, off, 8);
    }
    if ((c & 7) == 0) {
        int n = idx >> 6;
        g_as[n * 8 + (c >> 3)] = ps;
        g_ad[n * 8 + (c >> 3)] = pd;
    }
}

__global__ void att1_kernel(const float* __restrict__ asw, const float* __restrict__ adw) {
    int wid = (blockIdx.x * blockDim.x + threadIdx.x) >> 5;
    if (wid >= NN) return;
    int lane = threadIdx.x & 31;
    float v0 = g_xW[wid * 64 + lane];
    float v1 = g_xW[wid * 64 + lane + 32];
    float ps = v0 * __ldg(&asw[lane]) + v1 * __ldg(&asw[lane + 32]);
    float pd = v0 * __ldg(&adw[lane]) + v1 * __ldg(&adw[lane + 32]);
#pragma unroll
    for (int off = 16; off > 0; off >>= 1) {
        ps += __shfl_down_sync(FULL, ps, off);
        pd += __shfl_down_sync(FULL, pd, off);
    }
    if (lane == 0) { g_as[wid] = ps; g_ad[wid] = pd; }
}

// ================= fused softmax + aggregation: one warp per node =============
template <int H, bool WRITE_H>
__global__ __launch_bounds__(256) void agg_fused_kernel(const float* __restrict__ bias,
                                                        float* __restrict__ out) {
    int wid = (blockIdx.x * blockDim.x + threadIdx.x) >> 5;
    if (wid >= NN) return;
    int lane = threadIdx.x & 31;
    int n = wid;
    int beg = g_off[n], end = g_off[n + 1];
    int hj = (H == 8) ? (lane & 7) : 0;
    int j  = lane >> 3;
    float ad_a = g_ad[n * H + hj];

    // pass 1: segment max for head hj (4 edge slots x 8 head-lanes)
    float m = -INFINITY;
    for (int k = beg + j; k < end; k += 4) {
        int s = __ldg(&g_srcs[k]);
        m = fmaxf(m, leaky(__ldg(&g_as[s * H + hj]) + ad_a));
    }
    m = fmaxf(m, __shfl_xor_sync(FULL, m, 8));
    m = fmaxf(m, __shfl_xor_sync(FULL, m, 16));

    int h0 = (H == 8) ? (lane >> 3)     : 0;
    int h1 = (H == 8) ? (lane >> 3) + 4 : 0;
    float den = 0.f, num0 = 0.f, num1 = 0.f;

    // pass 2: exp + weighted gather, unnormalized
    for (int k = beg; k < end; k += 4) {
        int kk = k + j;
        int s_att = -1; float p = 0.f;
        if (kk < end) {
            s_att = __ldg(&g_srcs[kk]);
            p = expf(leaky(__ldg(&g_as[s_att * H + hj]) + ad_a) - m);
        }
        den += p;
#pragma unroll
        for (int j2 = 0; j2 < 4; j2++) {
            int   s2 = __shfl_sync(FULL, s_att, j2 * 8);
            float p0 = __shfl_sync(FULL, p, j2 * 8 + h0);
            float p1 = __shfl_sync(FULL, p, j2 * 8 + h1);
            if (s2 >= 0) {
                num0 = fmaf(p0, __ldg(&g_xW[s2 * 64 + lane]),      num0);
                num1 = fmaf(p1, __ldg(&g_xW[s2 * 64 + lane + 32]), num1);
            }
        }
    }
    den += __shfl_xor_sync(FULL, den, 8);
    den += __shfl_xor_sync(FULL, den, 16);
    float d0 = __shfl_sync(FULL, den, h0);
    float d1 = __shfl_sync(FULL, den, h1);

    float r0 = elu(num0 / d0 + __ldg(&bias[lane]));
    float r1 = elu(num1 / d1 + __ldg(&bias[lane + 32]));
    if (WRITE_H) {
        g_h[n * 64 + lane]      = r0;
        g_h[n * 64 + lane + 32] = r1;
    } else {
        out[n * 64 + lane]      = r0;
        out[n * 64 + lane + 32] = r1;
    }
}

// ================= launch =====================================================
extern "C" void kernel_launch(void* const* d_in, const int* in_sizes, int n_in,
                              void* d_out, int out_size) {
    const float* x   = (const float*)d_in[0];
    const int*   ei  = (const int*)  d_in[1];
    const float* W0  = (const float*)d_in[2];
    const float* as0 = (const float*)d_in[3];
    const float* ad0 = (const float*)d_in[4];
    const float* b0  = (const float*)d_in[5];
    const float* W1  = (const float*)d_in[6];
    const float* as1 = (const float*)d_in[7];
    const float* ad1 = (const float*)d_in[8];
    const float* b1  = (const float*)d_in[9];
    float* out = (float*)d_out;

    const int TB = 256;
    int g_n   = (NN + TB - 1) / TB;
    int g_e   = (ET + TB - 1) / TB;
    int g_nf  = (NN * 64 + TB - 1) / TB;
    int g_w   = (NN * 32 + TB - 1) / TB;     // one warp per node
    int g_lin = (NN + 63) / 64;

    // CSR build (shared by both layers)
    zero_cnt_kernel<<<g_n, TB>>>();
    hist_kernel<<<g_e, TB>>>(ei);
    scan_kernel<<<1, 1024>>>();
    scatter_kernel<<<g_e, TB>>>(ei);

    // layer 0 (H=8, C=8)
    lin0_kernel<<<g_lin, TB>>>(x, W0);
    att0_kernel<<<g_nf, TB>>>(as0, ad0);
    agg_fused_kernel<8, true><<<g_w, TB>>>(b0, nullptr);

    // layer 1 (H=1, C=64)
    lin1_kernel<<<g_lin, TB>>>(W1);
    att1_kernel<<<g_w, TB>>>(as1, ad1);
    agg_fused_kernel<1, false><<<g_w, TB>>>(b1, out);
}

// round 6
// speedup vs baseline: 2.1951x; 1.0878x over previous
#include <cuda_runtime.h>
#include <math.h>

#define NN 100000
#define EE 1600000
#define ET (EE + NN)          // edges incl. self-loops
#define FULL 0xFFFFFFFFu

// ---------------- scratch (device globals) -----------------------------------
__device__ __align__(16) float g_xW[NN * 64];   // features after linear
__device__ __align__(16) float g_h[NN * 64];    // layer-0 output
__device__ __align__(16) float g_as[NN * 8];    // src attention logits
__device__ __align__(16) float g_ad[NN * 8];    // dst attention logits
__device__ int g_cnt[NN];
__device__ int g_off[NN + 1];
__device__ int g_woff[NN];
__device__ int g_srcs[ET];

__device__ __forceinline__ float leaky(float v) { return v > 0.f ? v : 0.2f * v; }
__device__ __forceinline__ float elu(float v)   { return v > 0.f ? v : expm1f(v); }

__device__ __forceinline__ float dot4(float4 a, float4 b, float acc) {
    return fmaf(a.x, b.x, fmaf(a.y, b.y, fmaf(a.z, b.z, fmaf(a.w, b.w, acc))));
}

// ================= CSR build (counting sort by dst) ===========================
__global__ void zero_cnt_kernel() {
    int i = blockIdx.x * blockDim.x + threadIdx.x;
    if (i < NN) g_cnt[i] = 0;
}

__global__ void hist_kernel(const int* __restrict__ ei) {
    int e = blockIdx.x * blockDim.x + threadIdx.x;
    if (e >= ET) return;
    int d = (e < EE) ? __ldg(&ei[EE + e]) : (e - EE);
    atomicAdd(&g_cnt[d], 1);
}

__global__ void scan_kernel() {
    __shared__ int sums[1024];
    int t = threadIdx.x;
    const int CH = (NN + 1023) / 1024;
    int beg = t * CH, end = min(beg + CH, NN);
    int s = 0;
    for (int i = beg; i < end; i++) s += g_cnt[i];
    sums[t] = s;
    __syncthreads();
    for (int off = 1; off < 1024; off <<= 1) {
        int v = (t >= off) ? sums[t - off] : 0;
        __syncthreads();
        sums[t] += v;
        __syncthreads();
    }
    int run = sums[t] - s;               // exclusive base
    for (int i = beg; i < end; i++) {
        g_off[i] = run; g_woff[i] = run;
        run += g_cnt[i];
    }
    if (t == 0) g_off[NN] = ET;
}

__global__ void scatter_kernel(const int* __restrict__ ei) {
    int e = blockIdx.x * blockDim.x + threadIdx.x;
    if (e >= ET) return;
    int s, d;
    if (e < EE) { s = __ldg(&ei[e]); d = __ldg(&ei[EE + e]); }
    else        { s = e - EE; d = s; }
    int pos = atomicAdd(&g_woff[d], 1);
    g_srcs[pos] = s;
}

// ===== layer-0 linear: x[N,128] @ W0[128,64], attention dots fused ===========
__global__ __launch_bounds__(256) void lin0_kernel(const float* __restrict__ x,
                                                   const float* __restrict__ W0,
                                                   const float* __restrict__ asw,
                                                   const float* __restrict__ adw) {
    __shared__ float W0t[64 * 132];      // transposed, padded: W0t[c*132+k]
    __shared__ float xs[16 * 128];
    int t = threadIdx.x;
    for (int i = t; i < 128 * 64; i += 256) {
        int k = i >> 6, c = i & 63;
        W0t[c * 132 + k] = W0[i];
    }
    int c  = t & 15;
    int nl = t >> 4;
    // per-thread attention weights (4 channels)
    float s0 = __ldg(&asw[c]),      s1 = __ldg(&asw[c + 16]);
    float s2w = __ldg(&asw[c + 32]), s3 = __ldg(&asw[c + 48]);
    float d0 = __ldg(&adw[c]),      d1 = __ldg(&adw[c + 16]);
    float d2 = __ldg(&adw[c + 32]), d3 = __ldg(&adw[c + 48]);
    int hb = c >> 3;                 // head base (0 or 1); lanes group by 8
    int nodeBase = blockIdx.x * 64;
    for (int g = 0; g < 4; g++) {
        int base = nodeBase + g * 16;
        __syncthreads();
        for (int i = t; i < 512; i += 256) {       // 16 nodes x 32 float4
            int nn2 = i >> 5, kv = i & 31;
            int nd = base + nn2;
            float4 v = (nd < NN) ? ((const float4*)x)[nd * 32 + kv]
                                 : make_float4(0.f, 0.f, 0.f, 0.f);
            ((float4*)xs)[i] = v;
        }
        __syncthreads();
        int node = base + nl;
        if (node < NN) {
            float a0 = 0.f, a1 = 0.f, a2 = 0.f, a3 = 0.f;
#pragma unroll 8
            for (int k = 0; k < 128; k += 4) {
                float4 xv = *(const float4*)&xs[nl * 128 + k];
                a0 = dot4(xv, *(const float4*)&W0t[c * 132 + k],        a0);
                a1 = dot4(xv, *(const float4*)&W0t[(c + 16) * 132 + k], a1);
                a2 = dot4(xv, *(const float4*)&W0t[(c + 32) * 132 + k], a2);
                a3 = dot4(xv, *(const float4*)&W0t[(c + 48) * 132 + k], a3);
            }
            g_xW[node * 64 + c]      = a0;
            g_xW[node * 64 + c + 16] = a1;
            g_xW[node * 64 + c + 32] = a2;
            g_xW[node * 64 + c + 48] = a3;
            // fused attention dots: channels c,c+16,c+32,c+48 -> heads hb,hb+2,hb+4,hb+6
            float ps0 = a0 * s0, ps1 = a1 * s1, ps2 = a2 * s2w, ps3 = a3 * s3;
            float pd0 = a0 * d0, pd1 = a1 * d1, pd2 = a2 * d2,  pd3 = a3 * d3;
#pragma unroll
            for (int off = 4; off > 0; off >>= 1) {
                ps0 += __shfl_down_sync(FULL, ps0, off, 8);
                ps1 += __shfl_down_sync(FULL, ps1, off, 8);
                ps2 += __shfl_down_sync(FULL, ps2, off, 8);
                ps3 += __shfl_down_sync(FULL, ps3, off, 8);
                pd0 += __shfl_down_sync(FULL, pd0, off, 8);
                pd1 += __shfl_down_sync(FULL, pd1, off, 8);
                pd2 += __shfl_down_sync(FULL, pd2, off, 8);
                pd3 += __shfl_down_sync(FULL, pd3, off, 8);
            }
            if ((c & 7) == 0) {
                g_as[node * 8 + hb]     = ps0;
                g_as[node * 8 + hb + 2] = ps1;
                g_as[node * 8 + hb + 4] = ps2;
                g_as[node * 8 + hb + 6] = ps3;
                g_ad[node * 8 + hb]     = pd0;
                g_ad[node * 8 + hb + 2] = pd1;
                g_ad[node * 8 + hb + 4] = pd2;
                g_ad[node * 8 + hb + 6] = pd3;
            }
        }
    }
}

// ===== layer-1 linear: h[N,64] @ W1[64,64], attention dots fused (H=1) =======
__global__ __launch_bounds__(256) void lin1_kernel(const float* __restrict__ W1,
                                                   const float* __restrict__ asw,
                                                   const float* __restrict__ adw) {
    __shared__ float W1t[64 * 68];
    __shared__ float hs[16 * 64];
    int t = threadIdx.x;
    for (int i = t; i < 64 * 64; i += 256) {
        int k = i >> 6, c = i & 63;
        W1t[c * 68 + k] = W1[i];
    }
    int c  = t & 15;
    int nl = t >> 4;
    float s0 = __ldg(&asw[c]),      s1 = __ldg(&asw[c + 16]);
    float s2w = __ldg(&asw[c + 32]), s3 = __ldg(&asw[c + 48]);
    float d0 = __ldg(&adw[c]),      d1 = __ldg(&adw[c + 16]);
    float d2 = __ldg(&adw[c + 32]), d3 = __ldg(&adw[c + 48]);
    int nodeBase = blockIdx.x * 64;
    for (int g = 0; g < 4; g++) {
        int base = nodeBase + g * 16;
        __syncthreads();
        for (int i = t; i < 256; i += 256) {       // 16 nodes x 16 float4
            int nn2 = i >> 4, kv = i & 15;
            int nd = base + nn2;
            float4 v = (nd < NN) ? ((const float4*)g_h)[nd * 16 + kv]
                                 : make_float4(0.f, 0.f, 0.f, 0.f);
            ((float4*)hs)[i] = v;
        }
        __syncthreads();
        int node = base + nl;
        if (node < NN) {
            float a0 = 0.f, a1 = 0.f, a2 = 0.f, a3 = 0.f;
#pragma unroll 8
            for (int k = 0; k < 64; k += 4) {
                float4 xv = *(const float4*)&hs[nl * 64 + k];
                a0 = dot4(xv, *(const float4*)&W1t[c * 68 + k],        a0);
                a1 = dot4(xv, *(const float4*)&W1t[(c + 16) * 68 + k], a1);
                a2 = dot4(xv, *(const float4*)&W1t[(c + 32) * 68 + k], a2);
                a3 = dot4(xv, *(const float4*)&W1t[(c + 48) * 68 + k], a3);
            }
            g_xW[node * 64 + c]      = a0;
            g_xW[node * 64 + c + 16] = a1;
            g_xW[node * 64 + c + 32] = a2;
            g_xW[node * 64 + c + 48] = a3;
            // fused attention dots (single head): full 64-channel sum over 16 lanes
            float ps = a0 * s0 + a1 * s1 + a2 * s2w + a3 * s3;
            float pd = a0 * d0 + a1 * d1 + a2 * d2  + a3 * d3;
#pragma unroll
            for (int off = 8; off > 0; off >>= 1) {
                ps += __shfl_down_sync(FULL, ps, off, 16);
                pd += __shfl_down_sync(FULL, pd, off, 16);
            }
            if (c == 0) { g_as[node] = ps; g_ad[node] = pd; }
        }
    }
}

// ===== fused softmax + aggregation (single pass, no max subtraction) =========
// Safe here: logits are O(10) << 88, so exp never overflows; alpha identical.
template <bool WRITE_H>
__global__ __launch_bounds__(256) void agg8_kernel(const float* __restrict__ bias,
                                                   float* __restrict__ out) {
    int n = (blockIdx.x * blockDim.x + threadIdx.x) >> 5;
    if (n >= NN) return;
    int lane = threadIdx.x & 31;
    int beg = g_off[n], end = g_off[n + 1];
    int hj = lane & 7;                 // head for attention side
    int j  = lane >> 3;                // edge slot (4 per batch half)
    int h0 = lane >> 3, h1 = h0 + 4;   // heads owned on feature side
    float ad_a = g_ad[n * 8 + hj];

    float den = 0.f, num0 = 0.f, num1 = 0.f;
    for (int k = beg; k < end; k += 8) {
        int k0 = k + j, k1 = k + 4 + j;
        int sa = -1, sb = -1; float pa = 0.f, pb = 0.f;
        if (k0 < end) {
            sa = __ldg(&g_srcs[k0]);
            pa = __expf(leaky(__ldg(&g_as[sa * 8 + hj]) + ad_a));
        }
        if (k1 < end) {
            sb = __ldg(&g_srcs[k1]);
            pb = __expf(leaky(__ldg(&g_as[sb * 8 + hj]) + ad_a));
        }
        den += pa + pb;
#pragma unroll
        for (int j2 = 0; j2 < 4; j2++) {
            int   s2 = __shfl_sync(FULL, sa, j2 * 8);
            float p0 = __shfl_sync(FULL, pa, j2 * 8 + h0);
            float p1 = __shfl_sync(FULL, pa, j2 * 8 + h1);
            if (s2 >= 0) {
                num0 = fmaf(p0, __ldg(&g_xW[s2 * 64 + lane]),      num0);
                num1 = fmaf(p1, __ldg(&g_xW[s2 * 64 + lane + 32]), num1);
            }
        }
#pragma unroll
        for (int j2 = 0; j2 < 4; j2++) {
            int   s2 = __shfl_sync(FULL, sb, j2 * 8);
            float p0 = __shfl_sync(FULL, pb, j2 * 8 + h0);
            float p1 = __shfl_sync(FULL, pb, j2 * 8 + h1);
            if (s2 >= 0) {
                num0 = fmaf(p0, __ldg(&g_xW[s2 * 64 + lane]),      num0);
                num1 = fmaf(p1, __ldg(&g_xW[s2 * 64 + lane + 32]), num1);
            }
        }
    }
    den += __shfl_xor_sync(FULL, den, 8);
    den += __shfl_xor_sync(FULL, den, 16);
    float d0 = __shfl_sync(FULL, den, h0);
    float d1 = __shfl_sync(FULL, den, h1);

    float r0 = elu(num0 / d0 + __ldg(&bias[lane]));
    float r1 = elu(num1 / d1 + __ldg(&bias[lane + 32]));
    if (WRITE_H) {
        g_h[n * 64 + lane]      = r0;
        g_h[n * 64 + lane + 32] = r1;
    } else {
        out[n * 64 + lane]      = r0;
        out[n * 64 + lane + 32] = r1;
    }
}

template <bool WRITE_H>
__global__ __launch_bounds__(256) void agg1_kernel(const float* __restrict__ bias,
                                                   float* __restrict__ out) {
    int n = (blockIdx.x * blockDim.x + threadIdx.x) >> 5;
    if (n >= NN) return;
    int lane = threadIdx.x & 31;
    int beg = g_off[n], end = g_off[n + 1];
    float ad_a = g_ad[n];

    float den = 0.f, num0 = 0.f, num1 = 0.f;
    for (int k = beg; k < end; k += 32) {
        int kk = k + lane;
        int s = -1; float p = 0.f;
        if (kk < end) {
            s = __ldg(&g_srcs[kk]);
            p = __expf(leaky(__ldg(&g_as[s]) + ad_a));
        }
        den += p;
        int cnt = min(end - k, 32);
#pragma unroll 4
        for (int j2 = 0; j2 < cnt; j2++) {
            int   s2 = __shfl_sync(FULL, s, j2);
            float pp = __shfl_sync(FULL, p, j2);
            num0 = fmaf(pp, __ldg(&g_xW[s2 * 64 + lane]),      num0);
            num1 = fmaf(pp, __ldg(&g_xW[s2 * 64 + lane + 32]), num1);
        }
    }
#pragma unroll
    for (int off = 16; off > 0; off >>= 1)
        den += __shfl_xor_sync(FULL, den, off);

    float r0 = elu(num0 / den + __ldg(&bias[lane]));
    float r1 = elu(num1 / den + __ldg(&bias[lane + 32]));
    if (WRITE_H) {
        g_h[n * 64 + lane]      = r0;
        g_h[n * 64 + lane + 32] = r1;
    } else {
        out[n * 64 + lane]      = r0;
        out[n * 64 + lane + 32] = r1;
    }
}

// ================= launch =====================================================
extern "C" void kernel_launch(void* const* d_in, const int* in_sizes, int n_in,
                              void* d_out, int out_size) {
    const float* x   = (const float*)d_in[0];
    const int*   ei  = (const int*)  d_in[1];
    const float* W0  = (const float*)d_in[2];
    const float* as0 = (const float*)d_in[3];
    const float* ad0 = (const float*)d_in[4];
    const float* b0  = (const float*)d_in[5];
    const float* W1  = (const float*)d_in[6];
    const float* as1 = (const float*)d_in[7];
    const float* ad1 = (const float*)d_in[8];
    const float* b1  = (const float*)d_in[9];
    float* out = (float*)d_out;

    const int TB = 256;
    int g_n   = (NN + TB - 1) / TB;
    int g_e   = (ET + TB - 1) / TB;
    int g_w   = (NN * 32 + TB - 1) / TB;     // one warp per node
    int g_lin = (NN + 63) / 64;

    // CSR build (shared by both layers)
    zero_cnt_kernel<<<g_n, TB>>>();
    hist_kernel<<<g_e, TB>>>(ei);
    scan_kernel<<<1, 1024>>>();
    scatter_kernel<<<g_e, TB>>>(ei);

    // layer 0 (H=8, C=8)
    lin0_kernel<<<g_lin, TB>>>(x, W0, as0, ad0);
    agg8_kernel<true><<<g_w, TB>>>(b0, nullptr);

    // layer 1 (H=1, C=64)
    lin1_kernel<<<g_lin, TB>>>(W1, as1, ad1);
    agg1_kernel<false><<<g_w, TB>>>(b1, out);
}

// round 7
// speedup vs baseline: 2.3231x; 1.0583x over previous
#include <cuda_runtime.h>
#include <math.h>

#define NN 100000
#define EE 1600000
#define ET (EE + NN)          // edges incl. self-loops
#define FULL 0xFFFFFFFFu

// ---------------- scratch (device globals) -----------------------------------
__device__ __align__(16) float g_xW[NN * 64];   // features after linear
__device__ __align__(16) float g_h[NN * 64];    // layer-0 output
__device__ __align__(16) float g_as[NN * 8];    // src attention logits
__device__ __align__(16) float g_ad[NN * 8];    // dst attention logits
__device__ int g_cnt[NN];
__device__ int g_off[NN + 1];
__device__ int g_woff[NN];
__device__ int g_srcs[ET];

__device__ __forceinline__ float leaky(float v) { return v > 0.f ? v : 0.2f * v; }
__device__ __forceinline__ float elu(float v)   { return v > 0.f ? v : expm1f(v); }

__device__ __forceinline__ float dot4(float4 a, float4 b, float acc) {
    return fmaf(a.x, b.x, fmaf(a.y, b.y, fmaf(a.z, b.z, fmaf(a.w, b.w, acc))));
}

// ================= CSR build (counting sort by dst) ===========================
__global__ void zero_cnt_kernel() {
    int i = blockIdx.x * blockDim.x + threadIdx.x;
    if (i < NN) g_cnt[i] = 0;
}

__global__ void hist_kernel(const int* __restrict__ ei) {
    int e = blockIdx.x * blockDim.x + threadIdx.x;
    if (e >= ET) return;
    int d = (e < EE) ? __ldg(&ei[EE + e]) : (e - EE);
    atomicAdd(&g_cnt[d], 1);
}

__global__ void scan_kernel() {
    __shared__ int sums[1024];
    int t = threadIdx.x;
    const int CH = (NN + 1023) / 1024;
    int beg = t * CH, end = min(beg + CH, NN);
    int s = 0;
    for (int i = beg; i < end; i++) s += g_cnt[i];
    sums[t] = s;
    __syncthreads();
    for (int off = 1; off < 1024; off <<= 1) {
        int v = (t >= off) ? sums[t - off] : 0;
        __syncthreads();
        sums[t] += v;
        __syncthreads();
    }
    int run = sums[t] - s;               // exclusive base
    for (int i = beg; i < end; i++) {
        g_off[i] = run; g_woff[i] = run;
        run += g_cnt[i];
    }
    if (t == 0) g_off[NN] = ET;
}

__global__ void scatter_kernel(const int* __restrict__ ei) {
    int e = blockIdx.x * blockDim.x + threadIdx.x;
    if (e >= ET) return;
    int s, d;
    if (e < EE) { s = __ldg(&ei[e]); d = __ldg(&ei[EE + e]); }
    else        { s = e - EE; d = s; }
    int pos = atomicAdd(&g_woff[d], 1);
    g_srcs[pos] = s;
}

// ===== layer-0 linear: x[N,128] @ W0[128,64], attention dots fused ===========
__global__ __launch_bounds__(256) void lin0_kernel(const float* __restrict__ x,
                                                   const float* __restrict__ W0,
                                                   const float* __restrict__ asw,
                                                   const float* __restrict__ adw) {
    __shared__ float W0t[64 * 132];      // transposed, padded: W0t[c*132+k]
    __shared__ float xs[16 * 128];
    int t = threadIdx.x;
    for (int i = t; i < 128 * 64; i += 256) {
        int k = i >> 6, c = i & 63;
        W0t[c * 132 + k] = W0[i];
    }
    int c  = t & 15;
    int nl = t >> 4;
    float s0 = __ldg(&asw[c]),       s1 = __ldg(&asw[c + 16]);
    float s2w = __ldg(&asw[c + 32]), s3 = __ldg(&asw[c + 48]);
    float d0 = __ldg(&adw[c]),       d1 = __ldg(&adw[c + 16]);
    float d2 = __ldg(&adw[c + 32]),  d3 = __ldg(&adw[c + 48]);
    int hb = c >> 3;                 // head base (0 or 1)
    int nodeBase = blockIdx.x * 64;
    for (int g = 0; g < 4; g++) {
        int base = nodeBase + g * 16;
        __syncthreads();
        for (int i = t; i < 512; i += 256) {       // 16 nodes x 32 float4
            int nn2 = i >> 5, kv = i & 31;
            int nd = base + nn2;
            float4 v = (nd < NN) ? ((const float4*)x)[nd * 32 + kv]
                                 : make_float4(0.f, 0.f, 0.f, 0.f);
            ((float4*)xs)[i] = v;
        }
        __syncthreads();
        int node = base + nl;
        if (node < NN) {
            float a0 = 0.f, a1 = 0.f, a2 = 0.f, a3 = 0.f;
#pragma unroll 8
            for (int k = 0; k < 128; k += 4) {
                float4 xv = *(const float4*)&xs[nl * 128 + k];
                a0 = dot4(xv, *(const float4*)&W0t[c * 132 + k],        a0);
                a1 = dot4(xv, *(const float4*)&W0t[(c + 16) * 132 + k], a1);
                a2 = dot4(xv, *(const float4*)&W0t[(c + 32) * 132 + k], a2);
                a3 = dot4(xv, *(const float4*)&W0t[(c + 48) * 132 + k], a3);
            }
            g_xW[node * 64 + c]      = a0;
            g_xW[node * 64 + c + 16] = a1;
            g_xW[node * 64 + c + 32] = a2;
            g_xW[node * 64 + c + 48] = a3;
            float ps0 = a0 * s0, ps1 = a1 * s1, ps2 = a2 * s2w, ps3 = a3 * s3;
            float pd0 = a0 * d0, pd1 = a1 * d1, pd2 = a2 * d2,  pd3 = a3 * d3;
#pragma unroll
            for (int off = 4; off > 0; off >>= 1) {
                ps0 += __shfl_down_sync(FULL, ps0, off, 8);
                ps1 += __shfl_down_sync(FULL, ps1, off, 8);
                ps2 += __shfl_down_sync(FULL, ps2, off, 8);
                ps3 += __shfl_down_sync(FULL, ps3, off, 8);
                pd0 += __shfl_down_sync(FULL, pd0, off, 8);
                pd1 += __shfl_down_sync(FULL, pd1, off, 8);
                pd2 += __shfl_down_sync(FULL, pd2, off, 8);
                pd3 += __shfl_down_sync(FULL, pd3, off, 8);
            }
            if ((c & 7) == 0) {
                g_as[node * 8 + hb]     = ps0;
                g_as[node * 8 + hb + 2] = ps1;
                g_as[node * 8 + hb + 4] = ps2;
                g_as[node * 8 + hb + 6] = ps3;
                g_ad[node * 8 + hb]     = pd0;
                g_ad[node * 8 + hb + 2] = pd1;
                g_ad[node * 8 + hb + 4] = pd2;
                g_ad[node * 8 + hb + 6] = pd3;
            }
        }
    }
}

// ===== layer-1 linear: h[N,64] @ W1[64,64], attention dots fused (H=1) =======
__global__ __launch_bounds__(256) void lin1_kernel(const float* __restrict__ W1,
                                                   const float* __restrict__ asw,
                                                   const float* __restrict__ adw) {
    __shared__ float W1t[64 * 68];
    __shared__ float hs[16 * 64];
    int t = threadIdx.x;
    for (int i = t; i < 64 * 64; i += 256) {
        int k = i >> 6, c = i & 63;
        W1t[c * 68 + k] = W1[i];
    }
    int c  = t & 15;
    int nl = t >> 4;
    float s0 = __ldg(&asw[c]),       s1 = __ldg(&asw[c + 16]);
    float s2w = __ldg(&asw[c + 32]), s3 = __ldg(&asw[c + 48]);
    float d0 = __ldg(&adw[c]),       d1 = __ldg(&adw[c + 16]);
    float d2 = __ldg(&adw[c + 32]),  d3 = __ldg(&adw[c + 48]);
    int nodeBase = blockIdx.x * 64;
    for (int g = 0; g < 4; g++) {
        int base = nodeBase + g * 16;
        __syncthreads();
        for (int i = t; i < 256; i += 256) {
            int nn2 = i >> 4, kv = i & 15;
            int nd = base + nn2;
            float4 v = (nd < NN) ? ((const float4*)g_h)[nd * 16 + kv]
                                 : make_float4(0.f, 0.f, 0.f, 0.f);
            ((float4*)hs)[i] = v;
        }
        __syncthreads();
        int node = base + nl;
        if (node < NN) {
            float a0 = 0.f, a1 = 0.f, a2 = 0.f, a3 = 0.f;
#pragma unroll 8
            for (int k = 0; k < 64; k += 4) {
                float4 xv = *(const float4*)&hs[nl * 64 + k];
                a0 = dot4(xv, *(const float4*)&W1t[c * 68 + k],        a0);
                a1 = dot4(xv, *(const float4*)&W1t[(c + 16) * 68 + k], a1);
                a2 = dot4(xv, *(const float4*)&W1t[(c + 32) * 68 + k], a2);
                a3 = dot4(xv, *(const float4*)&W1t[(c + 48) * 68 + k], a3);
            }
            g_xW[node * 64 + c]      = a0;
            g_xW[node * 64 + c + 16] = a1;
            g_xW[node * 64 + c + 32] = a2;
            g_xW[node * 64 + c + 48] = a3;
            float ps = a0 * s0 + a1 * s1 + a2 * s2w + a3 * s3;
            float pd = a0 * d0 + a1 * d1 + a2 * d2  + a3 * d3;
#pragma unroll
            for (int off = 8; off > 0; off >>= 1) {
                ps += __shfl_down_sync(FULL, ps, off, 16);
                pd += __shfl_down_sync(FULL, pd, off, 16);
            }
            if (c == 0) { g_as[node] = ps; g_ad[node] = pd; }
        }
    }
}

// ===== fused softmax + aggregation v3: shuffle-free, float4 gathers ==========
// Warp = 1 node. Lane q = lane&15 owns channels 4q..4q+3 (head q>>1 for H=8).
// lane>>4 picks even/odd edge slots -> 2 edges in flight per warp iteration.
// No max subtraction (logits are O(10) << 88 — exp cannot overflow here).
template <int H, bool WRITE_H>
__global__ __launch_bounds__(256) void agg_kernel(const float* __restrict__ bias,
                                                  float* __restrict__ out) {
    int n = (blockIdx.x * blockDim.x + threadIdx.x) >> 5;
    if (n >= NN) return;
    int lane = threadIdx.x & 31;
    int half = lane >> 4;
    int q    = lane & 15;
    int h    = (H == 8) ? (q >> 1) : 0;
    int beg = g_off[n], end = g_off[n + 1];
    float ad_a = g_ad[n * H + h];

    float4 num = make_float4(0.f, 0.f, 0.f, 0.f);
    float  den = 0.f;
#pragma unroll 2
    for (int k = beg + half; k < end; k += 2) {
        int s = __ldg(&g_srcs[k]);
        float p = __expf(leaky(__ldg(&g_as[s * H + h]) + ad_a));
        den += p;
        float4 f = *(const float4*)&g_xW[s * 64 + q * 4];
        num.x = fmaf(p, f.x, num.x);
        num.y = fmaf(p, f.y, num.y);
        num.z = fmaf(p, f.z, num.z);
        num.w = fmaf(p, f.w, num.w);
    }
    // merge the two edge halves
    num.x += __shfl_xor_sync(FULL, num.x, 16);
    num.y += __shfl_xor_sync(FULL, num.y, 16);
    num.z += __shfl_xor_sync(FULL, num.z, 16);
    num.w += __shfl_xor_sync(FULL, num.w, 16);
    den   += __shfl_xor_sync(FULL, den, 16);

    if (half == 0) {
        float4 b4 = __ldg((const float4*)&bias[q * 4]);
        float inv = 1.f / den;
        float4 r;
        r.x = elu(num.x * inv + b4.x);
        r.y = elu(num.y * inv + b4.y);
        r.z = elu(num.z * inv + b4.z);
        r.w = elu(num.w * inv + b4.w);
        if (WRITE_H) ((float4*)g_h)[n * 16 + q] = r;
        else         ((float4*)out)[n * 16 + q] = r;
    }
}

// ================= launch =====================================================
extern "C" void kernel_launch(void* const* d_in, const int* in_sizes, int n_in,
                              void* d_out, int out_size) {
    const float* x   = (const float*)d_in[0];
    const int*   ei  = (const int*)  d_in[1];
    const float* W0  = (const float*)d_in[2];
    const float* as0 = (const float*)d_in[3];
    const float* ad0 = (const float*)d_in[4];
    const float* b0  = (const float*)d_in[5];
    const float* W1  = (const float*)d_in[6];
    const float* as1 = (const float*)d_in[7];
    const float* ad1 = (const float*)d_in[8];
    const float* b1  = (const float*)d_in[9];
    float* out = (float*)d_out;

    const int TB = 256;
    int g_n   = (NN + TB - 1) / TB;
    int g_e   = (ET + TB - 1) / TB;
    int g_w   = (NN * 32 + TB - 1) / TB;     // one warp per node
    int g_lin = (NN + 63) / 64;

    // CSR build (shared by both layers)
    zero_cnt_kernel<<<g_n, TB>>>();
    hist_kernel<<<g_e, TB>>>(ei);
    scan_kernel<<<1, 1024>>>();
    scatter_kernel<<<g_e, TB>>>(ei);

    // layer 0 (H=8, C=8)
    lin0_kernel<<<g_lin, TB>>>(x, W0, as0, ad0);
    agg_kernel<8, true><<<g_w, TB>>>(b0, nullptr);

    // layer 1 (H=1, C=64)
    lin1_kernel<<<g_lin, TB>>>(W1, as1, ad1);
    agg_kernel<1, false><<<g_w, TB>>>(b1, out);
}

// round 8
// speedup vs baseline: 2.9460x; 1.2682x over previous
#include <cuda_runtime.h>
#include <math.h>

#define NN 100000
#define EE 1600000
#define ET (EE + NN)          // edges incl. self-loops
#define FULL 0xFFFFFFFFu
#define NB ((NN + 255) / 256) // scan blocks = 391

// ---------------- scratch (device globals) -----------------------------------
__device__ __align__(16) float g_xW[NN * 64];   // features after linear
__device__ __align__(16) float g_h[NN * 64];    // layer-0 output
__device__ __align__(16) float g_as[NN * 8];    // src attention logits
__device__ __align__(16) float g_ad[NN * 8];    // dst attention logits
__device__ __align__(16) float g_den[NN * 8];   // softmax denominators
__device__ __align__(16) float g_p[ET * 8];     // per-(edge,head) exp values
__device__ int g_cnt[NN];
__device__ int g_off[NN + 1];
__device__ int g_woff[NN];
__device__ int g_srcs[ET];
__device__ int g_bsum[NB];
__device__ int g_bbase[NB];

__device__ __forceinline__ float leaky(float v) { return v > 0.f ? v : 0.2f * v; }
__device__ __forceinline__ float elu(float v)   { return v > 0.f ? v : expm1f(v); }

__device__ __forceinline__ float dot4(float4 a, float4 b, float acc) {
    return fmaf(a.x, b.x, fmaf(a.y, b.y, fmaf(a.z, b.z, fmaf(a.w, b.w, acc))));
}

// ================= CSR build (counting sort by dst) ===========================
__global__ void zero_cnt_kernel() {
    int i = blockIdx.x * blockDim.x + threadIdx.x;
    if (i < NN) g_cnt[i] = 0;
}

__global__ void hist_kernel(const int* __restrict__ ei) {
    int e = blockIdx.x * blockDim.x + threadIdx.x;
    if (e >= ET) return;
    int d = (e < EE) ? __ldg(&ei[EE + e]) : (e - EE);
    atomicAdd(&g_cnt[d], 1);
}

// per-block sums of 256-node chunks (coalesced)
__global__ void scan1_kernel() {
    __shared__ int sh[256];
    int t = threadIdx.x;
    int i = blockIdx.x * 256 + t;
    sh[t] = (i < NN) ? g_cnt[i] : 0;
    __syncthreads();
#pragma unroll
    for (int off = 128; off > 0; off >>= 1) {
        if (t < off) sh[t] += sh[t + off];
        __syncthreads();
    }
    if (t == 0) g_bsum[blockIdx.x] = sh[0];
}

// exclusive scan of the 391 block sums (single small block)
__global__ void scan2_kernel() {
    __shared__ int sh[512];
    int t = threadIdx.x;
    int v = (t < NB) ? g_bsum[t] : 0;
    sh[t] = v;
    __syncthreads();
#pragma unroll
    for (int off = 1; off < 512; off <<= 1) {
        int u = (t >= off) ? sh[t - off] : 0;
        __syncthreads();
        sh[t] += u;
        __syncthreads();
    }
    if (t < NB) g_bbase[t] = sh[t] - v;   // exclusive
    if (t == 0) g_off[NN] = ET;
}

// per-block exclusive scan + base -> offsets
__global__ void scan3_kernel() {
    __shared__ int sh[256];
    int t = threadIdx.x;
    int i = blockIdx.x * 256 + t;
    int c = (i < NN) ? g_cnt[i] : 0;
    sh[t] = c;
    __syncthreads();
#pragma unroll
    for (int off = 1; off < 256; off <<= 1) {
        int u = (t >= off) ? sh[t - off] : 0;
        __syncthreads();
        sh[t] += u;
        __syncthreads();
    }
    if (i < NN) {
        int o = g_bbase[blockIdx.x] + sh[t] - c;
        g_off[i]  = o;
        g_woff[i] = o;
    }
}

__global__ void scatter_kernel(const int* __restrict__ ei) {
    int e = blockIdx.x * blockDim.x + threadIdx.x;
    if (e >= ET) return;
    int s, d;
    if (e < EE) { s = __ldg(&ei[e]); d = __ldg(&ei[EE + e]); }
    else        { s = e - EE; d = s; }
    int pos = atomicAdd(&g_woff[d], 1);
    g_srcs[pos] = s;
}

// ===== layer-0 linear: x[N,128] @ W0[128,64], attention dots fused ===========
__global__ __launch_bounds__(256) void lin0_kernel(const float* __restrict__ x,
                                                   const float* __restrict__ W0,
                                                   const float* __restrict__ asw,
                                                   const float* __restrict__ adw) {
    __shared__ float W0t[64 * 132];
    __shared__ float xs[16 * 128];
    int t = threadIdx.x;
    for (int i = t; i < 128 * 64; i += 256) {
        int k = i >> 6, c = i & 63;
        W0t[c * 132 + k] = W0[i];
    }
    int c  = t & 15;
    int nl = t >> 4;
    float s0 = __ldg(&asw[c]),       s1 = __ldg(&asw[c + 16]);
    float s2w = __ldg(&asw[c + 32]), s3 = __ldg(&asw[c + 48]);
    float d0 = __ldg(&adw[c]),       d1 = __ldg(&adw[c + 16]);
    float d2 = __ldg(&adw[c + 32]),  d3 = __ldg(&adw[c + 48]);
    int hb = c >> 3;
    int nodeBase = blockIdx.x * 64;
    for (int g = 0; g < 4; g++) {
        int base = nodeBase + g * 16;
        __syncthreads();
        for (int i = t; i < 512; i += 256) {
            int nn2 = i >> 5, kv = i & 31;
            int nd = base + nn2;
            float4 v = (nd < NN) ? ((const float4*)x)[nd * 32 + kv]
                                 : make_float4(0.f, 0.f, 0.f, 0.f);
            ((float4*)xs)[i] = v;
        }
        __syncthreads();
        int node = base + nl;
        if (node < NN) {
            float a0 = 0.f, a1 = 0.f, a2 = 0.f, a3 = 0.f;
#pragma unroll 8
            for (int k = 0; k < 128; k += 4) {
                float4 xv = *(const float4*)&xs[nl * 128 + k];
                a0 = dot4(xv, *(const float4*)&W0t[c * 132 + k],        a0);
                a1 = dot4(xv, *(const float4*)&W0t[(c + 16) * 132 + k], a1);
                a2 = dot4(xv, *(const float4*)&W0t[(c + 32) * 132 + k], a2);
                a3 = dot4(xv, *(const float4*)&W0t[(c + 48) * 132 + k], a3);
            }
            g_xW[node * 64 + c]      = a0;
            g_xW[node * 64 + c + 16] = a1;
            g_xW[node * 64 + c + 32] = a2;
            g_xW[node * 64 + c + 48] = a3;
            float ps0 = a0 * s0, ps1 = a1 * s1, ps2 = a2 * s2w, ps3 = a3 * s3;
            float pd0 = a0 * d0, pd1 = a1 * d1, pd2 = a2 * d2,  pd3 = a3 * d3;
#pragma unroll
            for (int off = 4; off > 0; off >>= 1) {
                ps0 += __shfl_down_sync(FULL, ps0, off, 8);
                ps1 += __shfl_down_sync(FULL, ps1, off, 8);
                ps2 += __shfl_down_sync(FULL, ps2, off, 8);
                ps3 += __shfl_down_sync(FULL, ps3, off, 8);
                pd0 += __shfl_down_sync(FULL, pd0, off, 8);
                pd1 += __shfl_down_sync(FULL, pd1, off, 8);
                pd2 += __shfl_down_sync(FULL, pd2, off, 8);
                pd3 += __shfl_down_sync(FULL, pd3, off, 8);
            }
            if ((c & 7) == 0) {
                g_as[node * 8 + hb]     = ps0;
                g_as[node * 8 + hb + 2] = ps1;
                g_as[node * 8 + hb + 4] = ps2;
                g_as[node * 8 + hb + 6] = ps3;
                g_ad[node * 8 + hb]     = pd0;
                g_ad[node * 8 + hb + 2] = pd1;
                g_ad[node * 8 + hb + 4] = pd2;
                g_ad[node * 8 + hb + 6] = pd3;
            }
        }
    }
}

// ===== layer-1 linear: h[N,64] @ W1[64,64], attention dots fused (H=1) =======
__global__ __launch_bounds__(256) void lin1_kernel(const float* __restrict__ W1,
                                                   const float* __restrict__ asw,
                                                   const float* __restrict__ adw) {
    __shared__ float W1t[64 * 68];
    __shared__ float hs[16 * 64];
    int t = threadIdx.x;
    for (int i = t; i < 64 * 64; i += 256) {
        int k = i >> 6, c = i & 63;
        W1t[c * 68 + k] = W1[i];
    }
    int c  = t & 15;
    int nl = t >> 4;
    float s0 = __ldg(&asw[c]),       s1 = __ldg(&asw[c + 16]);
    float s2w = __ldg(&asw[c + 32]), s3 = __ldg(&asw[c + 48]);
    float d0 = __ldg(&adw[c]),       d1 = __ldg(&adw[c + 16]);
    float d2 = __ldg(&adw[c + 32]),  d3 = __ldg(&adw[c + 48]);
    int nodeBase = blockIdx.x * 64;
    for (int g = 0; g < 4; g++) {
        int base = nodeBase + g * 16;
        __syncthreads();
        for (int i = t; i < 256; i += 256) {
            int nn2 = i >> 4, kv = i & 15;
            int nd = base + nn2;
            float4 v = (nd < NN) ? ((const float4*)g_h)[nd * 16 + kv]
                                 : make_float4(0.f, 0.f, 0.f, 0.f);
            ((float4*)hs)[i] = v;
        }
        __syncthreads();
        int node = base + nl;
        if (node < NN) {
            float a0 = 0.f, a1 = 0.f, a2 = 0.f, a3 = 0.f;
#pragma unroll 8
            for (int k = 0; k < 64; k += 4) {
                float4 xv = *(const float4*)&hs[nl * 64 + k];
                a0 = dot4(xv, *(const float4*)&W1t[c * 68 + k],        a0);
                a1 = dot4(xv, *(const float4*)&W1t[(c + 16) * 68 + k], a1);
                a2 = dot4(xv, *(const float4*)&W1t[(c + 32) * 68 + k], a2);
                a3 = dot4(xv, *(const float4*)&W1t[(c + 48) * 68 + k], a3);
            }
            g_xW[node * 64 + c]      = a0;
            g_xW[node * 64 + c + 16] = a1;
            g_xW[node * 64 + c + 32] = a2;
            g_xW[node * 64 + c + 48] = a3;
            float ps = a0 * s0 + a1 * s1 + a2 * s2w + a3 * s3;
            float pd = a0 * d0 + a1 * d1 + a2 * d2  + a3 * d3;
#pragma unroll
            for (int off = 8; off > 0; off >>= 1) {
                ps += __shfl_down_sync(FULL, ps, off, 16);
                pd += __shfl_down_sync(FULL, pd, off, 16);
            }
            if (c == 0) { g_as[node] = ps; g_ad[node] = pd; }
        }
    }
}

// ===== pre-pass: per-(edge,head) exp + per-node denominators ==================
// Warp = node. Lane = j*8+h (j: 4 edge slots, h: 8 heads). Coalesced 128B writes.
// No max subtraction (logits O(10) << 88: exp cannot overflow).
__global__ __launch_bounds__(256) void pexp8_kernel() {
    int n = (blockIdx.x * blockDim.x + threadIdx.x) >> 5;
    if (n >= NN) return;
    int lane = threadIdx.x & 31;
    int h = lane & 7, j = lane >> 3;
    int beg = g_off[n], end = g_off[n + 1];
    float ad_a = g_ad[n * 8 + h];
    float den = 0.f;
    for (int k = beg + j; k < end; k += 4) {
        int s = __ldg(&g_srcs[k]);
        float p = __expf(leaky(__ldg(&g_as[s * 8 + h]) + ad_a));
        den += p;
        g_p[k * 8 + h] = p;
    }
    den += __shfl_xor_sync(FULL, den, 8);
    den += __shfl_xor_sync(FULL, den, 16);
    if (lane < 8) g_den[n * 8 + lane] = den;
}

__global__ __launch_bounds__(256) void pexp1_kernel() {
    int n = (blockIdx.x * blockDim.x + threadIdx.x) >> 5;
    if (n >= NN) return;
    int lane = threadIdx.x & 31;
    int beg = g_off[n], end = g_off[n + 1];
    float ad_a = g_ad[n];
    float den = 0.f;
    for (int k = beg + lane; k < end; k += 32) {
        int s = __ldg(&g_srcs[k]);
        float p = __expf(leaky(__ldg(&g_as[s]) + ad_a));
        den += p;
        g_p[k] = p;
    }
#pragma unroll
    for (int off = 16; off > 0; off >>= 1)
        den += __shfl_xor_sync(FULL, den, off);
    if (lane == 0) g_den[n] = den;
}

// ===== aggregation: p precomputed -> only s->xW dependent pair in loop ========
// Warp = node. Lane q = lane&15 owns channels 4q..4q+3; half = edge slot parity.
template <int H, bool WRITE_H>
__global__ __launch_bounds__(256) void agg_kernel(const float* __restrict__ bias,
                                                  float* __restrict__ out) {
    int n = (blockIdx.x * blockDim.x + threadIdx.x) >> 5;
    if (n >= NN) return;
    int lane = threadIdx.x & 31;
    int half = lane >> 4;
    int q    = lane & 15;
    int h    = (H == 8) ? (q >> 1) : 0;
    int beg = g_off[n], end = g_off[n + 1];
    float inv = 1.f / __ldg(&g_den[n * H + h]);

    float4 num = make_float4(0.f, 0.f, 0.f, 0.f);
#pragma unroll 4
    for (int k = beg + half; k < end; k += 2) {
        int s = __ldg(&g_srcs[k]);
        float p = __ldg(&g_p[(H == 8) ? (k * 8 + h) : k]);
        float4 f = *(const float4*)&g_xW[s * 64 + q * 4];
        num.x = fmaf(p, f.x, num.x);
        num.y = fmaf(p, f.y, num.y);
        num.z = fmaf(p, f.z, num.z);
        num.w = fmaf(p, f.w, num.w);
    }
    num.x += __shfl_xor_sync(FULL, num.x, 16);
    num.y += __shfl_xor_sync(FULL, num.y, 16);
    num.z += __shfl_xor_sync(FULL, num.z, 16);
    num.w += __shfl_xor_sync(FULL, num.w, 16);

    if (half == 0) {
        float4 b4 = __ldg((const float4*)&bias[q * 4]);
        float4 r;
        r.x = elu(num.x * inv + b4.x);
        r.y = elu(num.y * inv + b4.y);
        r.z = elu(num.z * inv + b4.z);
        r.w = elu(num.w * inv + b4.w);
        if (WRITE_H) ((float4*)g_h)[n * 16 + q] = r;
        else         ((float4*)out)[n * 16 + q] = r;
    }
}

// ================= launch =====================================================
extern "C" void kernel_launch(void* const* d_in, const int* in_sizes, int n_in,
                              void* d_out, int out_size) {
    const float* x   = (const float*)d_in[0];
    const int*   ei  = (const int*)  d_in[1];
    const float* W0  = (const float*)d_in[2];
    const float* as0 = (const float*)d_in[3];
    const float* ad0 = (const float*)d_in[4];
    const float* b0  = (const float*)d_in[5];
    const float* W1  = (const float*)d_in[6];
    const float* as1 = (const float*)d_in[7];
    const float* ad1 = (const float*)d_in[8];
    const float* b1  = (const float*)d_in[9];
    float* out = (float*)d_out;

    const int TB = 256;
    int g_n   = (NN + TB - 1) / TB;
    int g_e   = (ET + TB - 1) / TB;
    int g_w   = (NN * 32 + TB - 1) / TB;     // one warp per node
    int g_lin = (NN + 63) / 64;

    // CSR build (shared by both layers)
    zero_cnt_kernel<<<g_n, TB>>>();
    hist_kernel<<<g_e, TB>>>(ei);
    scan1_kernel<<<NB, 256>>>();
    scan2_kernel<<<1, 512>>>();
    scan3_kernel<<<NB, 256>>>();
    scatter_kernel<<<g_e, TB>>>(ei);

    // layer 0 (H=8, C=8)
    lin0_kernel<<<g_lin, TB>>>(x, W0, as0, ad0);
    pexp8_kernel<<<g_w, TB>>>();
    agg_kernel<8, true><<<g_w, TB>>>(b0, nullptr);

    // layer 1 (H=1, C=64)
    lin1_kernel<<<g_lin, TB>>>(W1, as1, ad1);
    pexp1_kernel<<<g_w, TB>>>();
    agg_kernel<1, false><<<g_w, TB>>>(b1, out);
}

// round 9
// speedup vs baseline: 3.0750x; 1.0438x over previous
#include <cuda_runtime.h>
#include <math.h>

#define NN 100000
#define EE 1600000
#define ET (EE + NN)          // edges incl. self-loops
#define FULL 0xFFFFFFFFu
#define NB ((NN + 255) / 256) // scan blocks = 391

// ---------------- scratch (device globals) -----------------------------------
__device__ __align__(16) float g_xW[NN * 64];   // features after linear
__device__ __align__(16) float g_h[NN * 64];    // layer-0 output
__device__ __align__(16) float g_as[NN * 8];    // src attention logits
__device__ __align__(16) float g_ad[NN * 8];    // dst attention logits
__device__ __align__(16) float g_den[NN * 8];   // softmax denominators
__device__ __align__(16) float g_p[ET * 8];     // per-(edge,head) exp values
__device__ int g_cnt[NN];
__device__ int g_off[NN + 1];
__device__ int g_woff[NN];
__device__ int g_srcs[ET];
__device__ int g_bsum[NB];
__device__ int g_bbase[NB];

__device__ __forceinline__ float leaky(float v) { return v > 0.f ? v : 0.2f * v; }
__device__ __forceinline__ float elu(float v)   { return v > 0.f ? v : expm1f(v); }

__device__ __forceinline__ float dot4(float4 a, float4 b, float acc) {
    return fmaf(a.x, b.x, fmaf(a.y, b.y, fmaf(a.z, b.z, fmaf(a.w, b.w, acc))));
}

// ================= CSR build (counting sort by dst) ===========================
__global__ void zero_cnt_kernel() {
    int i = blockIdx.x * blockDim.x + threadIdx.x;
    if (i < NN) g_cnt[i] = 0;
}

__global__ void hist_kernel(const int* __restrict__ ei) {
    int e = blockIdx.x * blockDim.x + threadIdx.x;
    if (e >= ET) return;
    int d = (e < EE) ? __ldg(&ei[EE + e]) : (e - EE);
    atomicAdd(&g_cnt[d], 1);
}

__global__ void scan1_kernel() {
    __shared__ int sh[256];
    int t = threadIdx.x;
    int i = blockIdx.x * 256 + t;
    sh[t] = (i < NN) ? g_cnt[i] : 0;
    __syncthreads();
#pragma unroll
    for (int off = 128; off > 0; off >>= 1) {
        if (t < off) sh[t] += sh[t + off];
        __syncthreads();
    }
    if (t == 0) g_bsum[blockIdx.x] = sh[0];
}

__global__ void scan2_kernel() {
    __shared__ int sh[512];
    int t = threadIdx.x;
    int v = (t < NB) ? g_bsum[t] : 0;
    sh[t] = v;
    __syncthreads();
#pragma unroll
    for (int off = 1; off < 512; off <<= 1) {
        int u = (t >= off) ? sh[t - off] : 0;
        __syncthreads();
        sh[t] += u;
        __syncthreads();
    }
    if (t < NB) g_bbase[t] = sh[t] - v;   // exclusive
    if (t == 0) g_off[NN] = ET;
}

__global__ void scan3_kernel() {
    __shared__ int sh[256];
    int t = threadIdx.x;
    int i = blockIdx.x * 256 + t;
    int c = (i < NN) ? g_cnt[i] : 0;
    sh[t] = c;
    __syncthreads();
#pragma unroll
    for (int off = 1; off < 256; off <<= 1) {
        int u = (t >= off) ? sh[t - off] : 0;
        __syncthreads();
        sh[t] += u;
        __syncthreads();
    }
    if (i < NN) {
        int o = g_bbase[blockIdx.x] + sh[t] - c;
        g_off[i]  = o;
        g_woff[i] = o;
    }
}

__global__ void scatter_kernel(const int* __restrict__ ei) {
    int e = blockIdx.x * blockDim.x + threadIdx.x;
    if (e >= ET) return;
    int s, d;
    if (e < EE) { s = __ldg(&ei[e]); d = __ldg(&ei[EE + e]); }
    else        { s = e - EE; d = s; }
    int pos = atomicAdd(&g_woff[d], 1);
    g_srcs[pos] = s;
}

// ===== layer-0 linear: x[N,128] @ W0[128,64], attention dots fused ===========
__global__ __launch_bounds__(256) void lin0_kernel(const float* __restrict__ x,
                                                   const float* __restrict__ W0,
                                                   const float* __restrict__ asw,
                                                   const float* __restrict__ adw) {
    __shared__ float W0t[64 * 132];
    __shared__ float xs[16 * 128];
    int t = threadIdx.x;
    for (int i = t; i < 128 * 64; i += 256) {
        int k = i >> 6, c = i & 63;
        W0t[c * 132 + k] = W0[i];
    }
    int c  = t & 15;
    int nl = t >> 4;
    float s0 = __ldg(&asw[c]),       s1 = __ldg(&asw[c + 16]);
    float s2w = __ldg(&asw[c + 32]), s3 = __ldg(&asw[c + 48]);
    float d0 = __ldg(&adw[c]),       d1 = __ldg(&adw[c + 16]);
    float d2 = __ldg(&adw[c + 32]),  d3 = __ldg(&adw[c + 48]);
    int hb = c >> 3;
    int nodeBase = blockIdx.x * 64;
    for (int g = 0; g < 4; g++) {
        int base = nodeBase + g * 16;
        __syncthreads();
        for (int i = t; i < 512; i += 256) {
            int nn2 = i >> 5, kv = i & 31;
            int nd = base + nn2;
            float4 v = (nd < NN) ? ((const float4*)x)[nd * 32 + kv]
                                 : make_float4(0.f, 0.f, 0.f, 0.f);
            ((float4*)xs)[i] = v;
        }
        __syncthreads();
        int node = base + nl;
        if (node < NN) {
            float a0 = 0.f, a1 = 0.f, a2 = 0.f, a3 = 0.f;
#pragma unroll 8
            for (int k = 0; k < 128; k += 4) {
                float4 xv = *(const float4*)&xs[nl * 128 + k];
                a0 = dot4(xv, *(const float4*)&W0t[c * 132 + k],        a0);
                a1 = dot4(xv, *(const float4*)&W0t[(c + 16) * 132 + k], a1);
                a2 = dot4(xv, *(const float4*)&W0t[(c + 32) * 132 + k], a2);
                a3 = dot4(xv, *(const float4*)&W0t[(c + 48) * 132 + k], a3);
            }
            g_xW[node * 64 + c]      = a0;
            g_xW[node * 64 + c + 16] = a1;
            g_xW[node * 64 + c + 32] = a2;
            g_xW[node * 64 + c + 48] = a3;
            float ps0 = a0 * s0, ps1 = a1 * s1, ps2 = a2 * s2w, ps3 = a3 * s3;
            float pd0 = a0 * d0, pd1 = a1 * d1, pd2 = a2 * d2,  pd3 = a3 * d3;
#pragma unroll
            for (int off = 4; off > 0; off >>= 1) {
                ps0 += __shfl_down_sync(FULL, ps0, off, 8);
                ps1 += __shfl_down_sync(FULL, ps1, off, 8);
                ps2 += __shfl_down_sync(FULL, ps2, off, 8);
                ps3 += __shfl_down_sync(FULL, ps3, off, 8);
                pd0 += __shfl_down_sync(FULL, pd0, off, 8);
                pd1 += __shfl_down_sync(FULL, pd1, off, 8);
                pd2 += __shfl_down_sync(FULL, pd2, off, 8);
                pd3 += __shfl_down_sync(FULL, pd3, off, 8);
            }
            if ((c & 7) == 0) {
                g_as[node * 8 + hb]     = ps0;
                g_as[node * 8 + hb + 2] = ps1;
                g_as[node * 8 + hb + 4] = ps2;
                g_as[node * 8 + hb + 6] = ps3;
                g_ad[node * 8 + hb]     = pd0;
                g_ad[node * 8 + hb + 2] = pd1;
                g_ad[node * 8 + hb + 4] = pd2;
                g_ad[node * 8 + hb + 6] = pd3;
            }
        }
    }
}

// ===== layer-1 linear: h[N,64] @ W1[64,64], attention dots fused (H=1) =======
__global__ __launch_bounds__(256) void lin1_kernel(const float* __restrict__ W1,
                                                   const float* __restrict__ asw,
                                                   const float* __restrict__ adw) {
    __shared__ float W1t[64 * 68];
    __shared__ float hs[16 * 64];
    int t = threadIdx.x;
    for (int i = t; i < 64 * 64; i += 256) {
        int k = i >> 6, c = i & 63;
        W1t[c * 68 + k] = W1[i];
    }
    int c  = t & 15;
    int nl = t >> 4;
    float s0 = __ldg(&asw[c]),       s1 = __ldg(&asw[c + 16]);
    float s2w = __ldg(&asw[c + 32]), s3 = __ldg(&asw[c + 48]);
    float d0 = __ldg(&adw[c]),       d1 = __ldg(&adw[c + 16]);
    float d2 = __ldg(&adw[c + 32]),  d3 = __ldg(&adw[c + 48]);
    int nodeBase = blockIdx.x * 64;
    for (int g = 0; g < 4; g++) {
        int base = nodeBase + g * 16;
        __syncthreads();
        for (int i = t; i < 256; i += 256) {
            int nn2 = i >> 4, kv = i & 15;
            int nd = base + nn2;
            float4 v = (nd < NN) ? ((const float4*)g_h)[nd * 16 + kv]
                                 : make_float4(0.f, 0.f, 0.f, 0.f);
            ((float4*)hs)[i] = v;
        }
        __syncthreads();
        int node = base + nl;
        if (node < NN) {
            float a0 = 0.f, a1 = 0.f, a2 = 0.f, a3 = 0.f;
#pragma unroll 8
            for (int k = 0; k < 64; k += 4) {
                float4 xv = *(const float4*)&hs[nl * 64 + k];
                a0 = dot4(xv, *(const float4*)&W1t[c * 68 + k],        a0);
                a1 = dot4(xv, *(const float4*)&W1t[(c + 16) * 68 + k], a1);
                a2 = dot4(xv, *(const float4*)&W1t[(c + 32) * 68 + k], a2);
                a3 = dot4(xv, *(const float4*)&W1t[(c + 48) * 68 + k], a3);
            }
            g_xW[node * 64 + c]      = a0;
            g_xW[node * 64 + c + 16] = a1;
            g_xW[node * 64 + c + 32] = a2;
            g_xW[node * 64 + c + 48] = a3;
            float ps = a0 * s0 + a1 * s1 + a2 * s2w + a3 * s3;
            float pd = a0 * d0 + a1 * d1 + a2 * d2  + a3 * d3;
#pragma unroll
            for (int off = 8; off > 0; off >>= 1) {
                ps += __shfl_down_sync(FULL, ps, off, 16);
                pd += __shfl_down_sync(FULL, pd, off, 16);
            }
            if (c == 0) { g_as[node] = ps; g_ad[node] = pd; }
        }
    }
}

// ===== pre-pass: per-(edge,head) exp + per-node denominators ==================
__global__ __launch_bounds__(256) void pexp8_kernel() {
    int n = (blockIdx.x * blockDim.x + threadIdx.x) >> 5;
    if (n >= NN) return;
    int lane = threadIdx.x & 31;
    int h = lane & 7, j = lane >> 3;
    int beg = g_off[n], end = g_off[n + 1];
    float ad_a = g_ad[n * 8 + h];
    float den = 0.f;
#pragma unroll 4
    for (int k = beg + j; k < end; k += 4) {
        int s = __ldg(&g_srcs[k]);
        float p = __expf(leaky(__ldg(&g_as[s * 8 + h]) + ad_a));
        den += p;
        g_p[k * 8 + h] = p;
    }
    den += __shfl_xor_sync(FULL, den, 8);
    den += __shfl_xor_sync(FULL, den, 16);
    if (lane < 8) g_den[n * 8 + lane] = den;
}

__global__ __launch_bounds__(256) void pexp1_kernel() {
    int n = (blockIdx.x * blockDim.x + threadIdx.x) >> 5;
    if (n >= NN) return;
    int lane = threadIdx.x & 31;
    int beg = g_off[n], end = g_off[n + 1];
    float ad_a = g_ad[n];
    float den = 0.f;
#pragma unroll 4
    for (int k = beg + lane; k < end; k += 32) {
        int s = __ldg(&g_srcs[k]);
        float p = __expf(leaky(__ldg(&g_as[s]) + ad_a));
        den += p;
        g_p[k] = p;
    }
#pragma unroll
    for (int off = 16; off > 0; off >>= 1)
        den += __shfl_xor_sync(FULL, den, off);
    if (lane == 0) g_den[n] = den;
}

// ===== aggregation =============================================================
template <int H, bool WRITE_H>
__global__ __launch_bounds__(256) void agg_kernel(const float* __restrict__ bias,
                                                  float* __restrict__ out) {
    int n = (blockIdx.x * blockDim.x + threadIdx.x) >> 5;
    if (n >= NN) return;
    int lane = threadIdx.x & 31;
    int half = lane >> 4;
    int q    = lane & 15;
    int h    = (H == 8) ? (q >> 1) : 0;
    int beg = g_off[n], end = g_off[n + 1];
    float inv = 1.f / __ldg(&g_den[n * H + h]);

    float4 num = make_float4(0.f, 0.f, 0.f, 0.f);
#pragma unroll 4
    for (int k = beg + half; k < end; k += 2) {
        int s = __ldg(&g_srcs[k]);
        float p = __ldg(&g_p[(H == 8) ? (k * 8 + h) : k]);
        float4 f = *(const float4*)&g_xW[s * 64 + q * 4];
        num.x = fmaf(p, f.x, num.x);
        num.y = fmaf(p, f.y, num.y);
        num.z = fmaf(p, f.z, num.z);
        num.w = fmaf(p, f.w, num.w);
    }
    num.x += __shfl_xor_sync(FULL, num.x, 16);
    num.y += __shfl_xor_sync(FULL, num.y, 16);
    num.z += __shfl_xor_sync(FULL, num.z, 16);
    num.w += __shfl_xor_sync(FULL, num.w, 16);

    if (half == 0) {
        float4 b4 = __ldg((const float4*)&bias[q * 4]);
        float4 r;
        r.x = elu(num.x * inv + b4.x);
        r.y = elu(num.y * inv + b4.y);
        r.z = elu(num.z * inv + b4.z);
        r.w = elu(num.w * inv + b4.w);
        if (WRITE_H) ((float4*)g_h)[n * 16 + q] = r;
        else         ((float4*)out)[n * 16 + q] = r;
    }
}

// ================= launch =====================================================
extern "C" void kernel_launch(void* const* d_in, const int* in_sizes, int n_in,
                              void* d_out, int out_size) {
    const float* x   = (const float*)d_in[0];
    const int*   ei  = (const int*)  d_in[1];
    const float* W0  = (const float*)d_in[2];
    const float* as0 = (const float*)d_in[3];
    const float* ad0 = (const float*)d_in[4];
    const float* b0  = (const float*)d_in[5];
    const float* W1  = (const float*)d_in[6];
    const float* as1 = (const float*)d_in[7];
    const float* ad1 = (const float*)d_in[8];
    const float* b1  = (const float*)d_in[9];
    float* out = (float*)d_out;

    // Lazily created side stream + events (host objects only; no device memory).
    static cudaStream_t s2 = nullptr;
    static cudaEvent_t ev_fork = nullptr, ev_lin0 = nullptr;
    if (!s2) {
        cudaStreamCreateWithFlags(&s2, cudaStreamNonBlocking);
        cudaEventCreateWithFlags(&ev_fork, cudaEventDisableTiming);
        cudaEventCreateWithFlags(&ev_lin0, cudaEventDisableTiming);
    }

    const int TB = 256;
    int g_n   = (NN + TB - 1) / TB;
    int g_e   = (ET + TB - 1) / TB;
    int g_w   = (NN * 32 + TB - 1) / TB;     // one warp per node
    int g_lin = (NN + 63) / 64;

    // Fork: lin0 runs concurrently with the CSR build.
    cudaEventRecord(ev_fork, 0);
    cudaStreamWaitEvent(s2, ev_fork, 0);
    lin0_kernel<<<g_lin, TB, 0, s2>>>(x, W0, as0, ad0);
    cudaEventRecord(ev_lin0, s2);

    // CSR build on the main stream.
    zero_cnt_kernel<<<g_n, TB>>>();
    hist_kernel<<<g_e, TB>>>(ei);
    scan1_kernel<<<NB, 256>>>();
    scan2_kernel<<<1, 512>>>();
    scan3_kernel<<<NB, 256>>>();
    scatter_kernel<<<g_e, TB>>>(ei);

    // Join: pexp8 needs both CSR and lin0 outputs.
    cudaStreamWaitEvent(0, ev_lin0, 0);

    // layer 0 (H=8, C=8)
    pexp8_kernel<<<g_w, TB>>>();
    agg_kernel<8, true><<<g_w, TB>>>(b0, nullptr);

    // layer 1 (H=1, C=64)
    lin1_kernel<<<g_lin, TB>>>(W1, as1, ad1);
    pexp1_kernel<<<g_w, TB>>>();
    agg_kernel<1, false><<<g_w, TB>>>(b1, out);
}